// round 3
// baseline (speedup 1.0000x reference)
#include <cuda_runtime.h>

#define HH 256
#define WW 256
#define BB 2
#define CC 21
#define KF 7
#define SPAN 3
#define KK 49
#define HW (HH*WW)

// Tile config: 32 wide x 8 tall, 256 threads, one thread per pixel.
#define TX 32
#define TY 8
#define NPIX (TX*TY)           // 256
#define HALO_W (TX + 2*SPAN)   // 38
#define HALO_H (TY + 2*SPAN)   // 14
#define HALO_N (HALO_W * HALO_H)  // 532

// Scratch (no allocations allowed -> __device__ globals)
__device__ float g_gauss[BB*KK*HW];       // [b][k][h][w]
__device__ float g_lgu[BB*CC*HW];         // log-softmax(unary)
__device__ float g_pred[2][BB*CC*HW];     // ping-pong prediction buffers

// ---------------------------------------------------------------------------
// Kernel A: pairwise Gaussian weights (pos + color), computed once.
// ---------------------------------------------------------------------------
__global__ __launch_bounds__(256) void gauss_kernel(const float* __restrict__ img) {
    __shared__ float simg[3][HALO_H][HALO_W];
    const int b  = blockIdx.z;
    const int tx = threadIdx.x, ty = threadIdx.y;
    const int tid = ty * TX + tx;
    const int h0 = blockIdx.y * TY, w0 = blockIdx.x * TX;

    for (int idx = tid; idx < 3 * HALO_N; idx += 256) {
        int ch = idx / HALO_N;
        int rem = idx % HALO_N;
        int r = rem / HALO_W, c = rem % HALO_W;
        int gh = h0 - SPAN + r, gw = w0 - SPAN + c;
        float v = 0.f;
        if (gh >= 0 && gh < HH && gw >= 0 && gw < WW)
            v = img[(b*3 + ch)*HW + gh*WW + gw] * (1.f/13.f);
        simg[ch][r][c] = v;
    }
    __syncthreads();

    const int h = h0 + ty, w = w0 + tx;
    const float c0 = simg[0][ty+SPAN][tx+SPAN];
    const float c1 = simg[1][ty+SPAN][tx+SPAN];
    const float c2 = simg[2][ty+SPAN][tx+SPAN];

    #pragma unroll
    for (int i = 0; i < KF; i++) {
        #pragma unroll
        for (int j = 0; j < KF; j++) {
            const int k = i*KF + j;
            const int dh = i - SPAN, dw = j - SPAN;
            const int nh = h + dh, nw = w + dw;
            float g = 0.f;
            if (nh >= 0 && nh < HH && nw >= 0 && nw < WW) {
                float d0 = simg[0][ty+i][tx+j] - c0;
                float d1 = simg[1][ty+i][tx+j] - c1;
                float d2 = simg[2][ty+i][tx+j] - c2;
                float col = __expf(-0.5f*(d0*d0 + d1*d1 + d2*d2));
                float pos = __expf(-(float)(dh*dh + dw*dw) * (0.5f/9.f));
                g = 3.f*pos + 10.f*col;
            }
            g_gauss[(b*KK + k)*HW + h*WW + w] = g;
        }
    }
}

// ---------------------------------------------------------------------------
// Kernel B: log_softmax over classes; seeds prediction buffer 0.
// ---------------------------------------------------------------------------
__global__ __launch_bounds__(256) void lsm_kernel(const float* __restrict__ unary) {
    int idx = blockIdx.x * blockDim.x + threadIdx.x;   // over B*HW
    if (idx >= BB*HW) return;
    int b = idx / HW, p = idx % HW;
    const float* u = unary + b*CC*HW + p;

    float v[CC];
    float mx = -1e30f;
    #pragma unroll
    for (int c = 0; c < CC; c++) { v[c] = u[c*HW]; mx = fmaxf(mx, v[c]); }
    float s = 0.f;
    #pragma unroll
    for (int c = 0; c < CC; c++) s += __expf(v[c] - mx);
    float lse = mx + __logf(s);
    #pragma unroll
    for (int c = 0; c < CC; c++) {
        float lg = v[c] - lse;
        g_lgu[(b*CC + c)*HW + p]      = lg;
        g_pred[0][(b*CC + c)*HW + p]  = lg;
    }
}

// ---------------------------------------------------------------------------
// Kernel C: one mean-field iteration — software-pipelined class loop.
//   * gaussian (49 taps) in registers, reused across all 21 classes
//   * double-buffered smem halo: prefetch class c+1 into regs while
//     computing class c -> ONE barrier per class, LDG latency hidden
//   * per-class results m[] kept in smem [CC][NPIX] (conflict-free) to cut
//     register pressure -> 3 blocks/SM
// ---------------------------------------------------------------------------
__global__ __launch_bounds__(256, 3) void iter_kernel(const float* __restrict__ wt,
                                                      float* __restrict__ dout,
                                                      int it) {
    __shared__ float sp[2][HALO_N];      // double-buffered halo (4.3 KB)
    __shared__ float sm_m[CC * NPIX];    // per-class results (21.5 KB)
    __shared__ float sw[CC];

    const float* __restrict__ pin = g_pred[it & 1];
    float* __restrict__ pout = (it == 4) ? dout : g_pred[(it + 1) & 1];
    const int do_sm = (it != 4);

    const int b  = blockIdx.z;
    const int tx = threadIdx.x, ty = threadIdx.y;
    const int tid = ty * TX + tx;
    const int h0 = blockIdx.y * TY, w0 = blockIdx.x * TX;
    const int h = h0 + ty, w = w0 + tx;
    const int pix = h*WW + w;

    if (tid < CC) sw[tid] = wt[tid];

    // ---- halo-load plan: 532 = 256 + 256 + 20; slot2 only for tid < 20 ----
    int g0, g1, g2; float ok0, ok1, ok2;
    {
        int idx0 = tid, idx1 = tid + 256, idx2 = tid + 512;
        int r, c, gh, gw;
        r = idx0 / HALO_W; c = idx0 % HALO_W;
        gh = h0 - SPAN + r; gw = w0 - SPAN + c;
        ok0 = (gh >= 0 && gh < HH && gw >= 0 && gw < WW) ? 1.f : 0.f;
        g0 = min(max(gh,0),HH-1)*WW + min(max(gw,0),WW-1);
        r = idx1 / HALO_W; c = idx1 % HALO_W;
        gh = h0 - SPAN + r; gw = w0 - SPAN + c;
        ok1 = (gh >= 0 && gh < HH && gw >= 0 && gw < WW) ? 1.f : 0.f;
        g1 = min(max(gh,0),HH-1)*WW + min(max(gw,0),WW-1);
        r = idx2 / HALO_W; c = idx2 % HALO_W;
        gh = h0 - SPAN + r; gw = w0 - SPAN + c;
        ok2 = (idx2 < HALO_N && gh >= 0 && gh < HH && gw >= 0 && gw < WW) ? 1.f : 0.f;
        gh = min(max(gh,0),HH-1); gw = min(max(gw,0),WW-1);
        g2 = gh*WW + gw;
    }
    const bool has2 = (tid < HALO_N - 512);   // tid < 20

    // ---- prefetch class 0 halo ----
    const float* pc = pin + b*CC*HW;
    float p0 = pc[g0]*ok0, p1 = pc[g1]*ok1, p2 = has2 ? pc[g2]*ok2 : 0.f;

    // ---- gaussian taps -> registers (49 outstanding LDGs overlap) ----
    float gr[KK];
    #pragma unroll
    for (int k = 0; k < KK; k++)
        gr[k] = g_gauss[(b*KK + k)*HW + pix];

    // commit class 0, prefetch class 1
    sp[0][tid] = p0; sp[0][tid+256] = p1; if (has2) sp[0][tid+512] = p2;
    pc += HW;
    p0 = pc[g0]*ok0; p1 = pc[g1]*ok1; p2 = has2 ? pc[g2]*ok2 : 0.f;
    float lg_cur = g_lgu[(b*CC + 0)*HW + pix];
    float lg_nxt = g_lgu[(b*CC + 1)*HW + pix];
    __syncthreads();

    float run_max = -1e30f;
    const int sbase = ty*HALO_W + tx;

    #pragma unroll 1
    for (int c = 0; c < CC; c++) {
        const float* __restrict__ s = sp[c & 1] + sbase;
        float acc = 0.f;
        #pragma unroll
        for (int i = 0; i < KF; i++) {
            #pragma unroll
            for (int j = 0; j < KF; j++)
                acc = fmaf(gr[i*KF + j], s[i*HALO_W + j], acc);
        }
        float wc = sw[c];
        float val = fmaf(wc, acc - lg_cur, lg_cur);   // (1-wc)*lg + wc*acc
        sm_m[c*NPIX + tid] = val;
        run_max = fmaxf(run_max, val);

        if (c + 1 < CC) {
            float* d = sp[(c + 1) & 1];
            d[tid] = p0; d[tid+256] = p1; if (has2) d[tid+512] = p2;
            lg_cur = lg_nxt;
            if (c + 2 < CC) {
                pc += HW;
                p0 = pc[g0]*ok0; p1 = pc[g1]*ok1; p2 = has2 ? pc[g2]*ok2 : 0.f;
                lg_nxt = g_lgu[(b*CC + c + 2)*HW + pix];
            }
            __syncthreads();
        }
    }

    // ---- softmax over classes (from smem) + store ----
    float* po = pout + b*CC*HW + pix;
    if (do_sm) {
        float s = 0.f;
        #pragma unroll 1
        for (int c = 0; c < CC; c++) {
            float e = __expf(sm_m[c*NPIX + tid] - run_max);
            s += e;
            sm_m[c*NPIX + tid] = e;
        }
        float inv = 1.f / s;
        #pragma unroll 1
        for (int c = 0; c < CC; c++)
            po[c*HW] = sm_m[c*NPIX + tid] * inv;
    } else {
        #pragma unroll 1
        for (int c = 0; c < CC; c++)
            po[c*HW] = sm_m[c*NPIX + tid];
    }
}

// ---------------------------------------------------------------------------
extern "C" void kernel_launch(void* const* d_in, const int* in_sizes, int n_in,
                              void* d_out, int out_size) {
    const float* unary  = nullptr;   // 2*21*256*256 = 2752512
    const float* img    = nullptr;   // 2*3*256*256  = 393216
    const float* weight = nullptr;   // 21
    for (int i = 0; i < n_in; i++) {
        if (in_sizes[i] == BB*CC*HW)      unary  = (const float*)d_in[i];
        else if (in_sizes[i] == BB*3*HW)  img    = (const float*)d_in[i];
        else if (in_sizes[i] == CC)       weight = (const float*)d_in[i];
        // num_iter (1 elem) fixed at 5 by problem setup.
    }
    float* out = (float*)d_out;

    dim3 blk(TX, TY);
    dim3 grd(WW/TX, HH/TY, BB);           // 8 x 32 x 2 = 512 blocks

    gauss_kernel<<<grd, blk>>>(img);
    lsm_kernel<<<(BB*HW + 255)/256, 256>>>(unary);
    for (int it = 0; it < 5; it++)
        iter_kernel<<<grd, blk>>>(weight, out, it);
}

// round 6
// speedup vs baseline: 1.9104x; 1.9104x over previous
#include <cuda_runtime.h>

#define HH 256
#define WW 256
#define BB 2
#define CC 21
#define KF 7
#define SPAN 3
#define KK 49
#define HW (HH*WW)

// Tile config: 32 wide x 8 tall, 256 threads, one thread per pixel.
#define TX 32
#define TY 8
#define NPIX (TX*TY)           // 256
#define HALO_W (TX + 2*SPAN)   // 38
#define HALO_H (TY + 2*SPAN)   // 14
#define HALO_N (HALO_W * HALO_H)  // 532

// Scratch (no allocations allowed -> __device__ globals)
__device__ float g_gauss[BB*KK*HW];       // [b][k][h][w]
__device__ float g_lgu[BB*CC*HW];         // log-softmax(unary)
__device__ float g_pred[2][BB*CC*HW];     // ping-pong prediction buffers

// ---------------------------------------------------------------------------
// Kernel A: pairwise Gaussian weights (pos + color), computed once.
// ---------------------------------------------------------------------------
__global__ __launch_bounds__(256) void gauss_kernel(const float* __restrict__ img) {
    __shared__ float simg[3][HALO_H][HALO_W];
    const int b  = blockIdx.z;
    const int tx = threadIdx.x, ty = threadIdx.y;
    const int tid = ty * TX + tx;
    const int h0 = blockIdx.y * TY, w0 = blockIdx.x * TX;

    for (int idx = tid; idx < 3 * HALO_N; idx += 256) {
        int ch = idx / HALO_N;
        int rem = idx % HALO_N;
        int r = rem / HALO_W, c = rem % HALO_W;
        int gh = h0 - SPAN + r, gw = w0 - SPAN + c;
        float v = 0.f;
        if (gh >= 0 && gh < HH && gw >= 0 && gw < WW)
            v = img[(b*3 + ch)*HW + gh*WW + gw] * (1.f/13.f);
        simg[ch][r][c] = v;
    }
    __syncthreads();

    const int h = h0 + ty, w = w0 + tx;
    const float c0 = simg[0][ty+SPAN][tx+SPAN];
    const float c1 = simg[1][ty+SPAN][tx+SPAN];
    const float c2 = simg[2][ty+SPAN][tx+SPAN];

    #pragma unroll
    for (int i = 0; i < KF; i++) {
        #pragma unroll
        for (int j = 0; j < KF; j++) {
            const int k = i*KF + j;
            const int dh = i - SPAN, dw = j - SPAN;
            const int nh = h + dh, nw = w + dw;
            float g = 0.f;
            if (nh >= 0 && nh < HH && nw >= 0 && nw < WW) {
                float d0 = simg[0][ty+i][tx+j] - c0;
                float d1 = simg[1][ty+i][tx+j] - c1;
                float d2 = simg[2][ty+i][tx+j] - c2;
                float col = __expf(-0.5f*(d0*d0 + d1*d1 + d2*d2));
                float pos = __expf(-(float)(dh*dh + dw*dw) * (0.5f/9.f));
                g = 3.f*pos + 10.f*col;
            }
            g_gauss[(b*KK + k)*HW + h*WW + w] = g;
        }
    }
}

// ---------------------------------------------------------------------------
// Kernel B: log_softmax over classes; seeds prediction buffer 0.
// ---------------------------------------------------------------------------
__global__ __launch_bounds__(256) void lsm_kernel(const float* __restrict__ unary) {
    int idx = blockIdx.x * blockDim.x + threadIdx.x;   // over B*HW
    if (idx >= BB*HW) return;
    int b = idx / HW, p = idx % HW;
    const float* u = unary + b*CC*HW + p;

    float v[CC];
    float mx = -1e30f;
    #pragma unroll
    for (int c = 0; c < CC; c++) { v[c] = u[c*HW]; mx = fmaxf(mx, v[c]); }
    float s = 0.f;
    #pragma unroll
    for (int c = 0; c < CC; c++) s += __expf(v[c] - mx);
    float lse = mx + __logf(s);
    #pragma unroll
    for (int c = 0; c < CC; c++) {
        float lg = v[c] - lse;
        g_lgu[(b*CC + c)*HW + p]      = lg;
        g_pred[0][(b*CC + c)*HW + p]  = lg;
    }
}

// ---------------------------------------------------------------------------
// Kernel C: one mean-field iteration — ALL class tiles staged in smem.
//   * load all 21 class halo tiles up-front (max MLP), ONE barrier total
//   * gaussian (49 taps) in registers, reused across all 21 classes
//   * barrier-free compute: 21 x 49 FMA straight from smem (conflict-free:
//     each warp is one image row -> 32 consecutive floats per tap)
//   * m[21] accumulators + softmax entirely in registers
// ---------------------------------------------------------------------------
__global__ __launch_bounds__(256, 2) void iter_kernel(const float* __restrict__ wt,
                                                      float* __restrict__ dout,
                                                      int it) {
    __shared__ float sp[CC][HALO_N];     // 21 x 532 floats = 44.7 KB
    __shared__ float sw[CC];

    const float* __restrict__ pin = g_pred[it & 1];
    float* __restrict__ pout = (it == 4) ? dout : g_pred[(it + 1) & 1];
    const int do_sm = (it != 4);

    const int b  = blockIdx.z;
    const int tx = threadIdx.x, ty = threadIdx.y;
    const int tid = ty * TX + tx;
    const int h0 = blockIdx.y * TY, w0 = blockIdx.x * TX;
    const int h = h0 + ty, w = w0 + tx;
    const int pix = h*WW + w;

    if (tid < CC) sw[tid] = wt[tid];

    // ---- halo-load plan: 532 = 256 + 256 + 20; slot2 only for tid < 20 ----
    int g0, g1, g2; float ok0, ok1, ok2;
    {
        int r, c, gh, gw;
        r = tid / HALO_W; c = tid % HALO_W;
        gh = h0 - SPAN + r; gw = w0 - SPAN + c;
        ok0 = (gh >= 0 && gh < HH && gw >= 0 && gw < WW) ? 1.f : 0.f;
        g0 = min(max(gh,0),HH-1)*WW + min(max(gw,0),WW-1);
        int i1 = tid + 256;
        r = i1 / HALO_W; c = i1 % HALO_W;
        gh = h0 - SPAN + r; gw = w0 - SPAN + c;
        ok1 = (gh >= 0 && gh < HH && gw >= 0 && gw < WW) ? 1.f : 0.f;
        g1 = min(max(gh,0),HH-1)*WW + min(max(gw,0),WW-1);
        int i2 = tid + 512;
        r = i2 / HALO_W; c = i2 % HALO_W;
        gh = h0 - SPAN + r; gw = w0 - SPAN + c;
        ok2 = (i2 < HALO_N && gh >= 0 && gh < HH && gw >= 0 && gw < WW) ? 1.f : 0.f;
        g2 = min(max(gh,0),HH-1)*WW + min(max(gw,0),WW-1);
    }
    const bool has2 = (tid < HALO_N - 512);   // tid < 20

    // ---- stage all 21 class halo tiles (independent LDGs, huge MLP) ----
    {
        const float* pc = pin + b*CC*HW;
        #pragma unroll
        for (int c = 0; c < CC; c++, pc += HW) {
            sp[c][tid]       = pc[g0] * ok0;
            sp[c][tid + 256] = pc[g1] * ok1;
            if (has2) sp[c][tid + 512] = pc[g2] * ok2;
        }
    }

    // ---- gaussian taps -> registers (overlaps with halo loads) ----
    float gr[KK];
    #pragma unroll
    for (int k = 0; k < KK; k++)
        gr[k] = g_gauss[(b*KK + k)*HW + pix];

    __syncthreads();   // the ONLY barrier

    // ---- barrier-free compute: 21 classes x 49 taps ----
    const int sbase = ty*HALO_W + tx;
    const float* __restrict__ lgu = g_lgu + b*CC*HW + pix;
    float m[CC];
    #pragma unroll
    for (int c = 0; c < CC; c++) {
        const float* __restrict__ s = sp[c] + sbase;
        float acc = 0.f;
        #pragma unroll
        for (int i = 0; i < KF; i++) {
            #pragma unroll
            for (int j = 0; j < KF; j++)
                acc = fmaf(gr[i*KF + j], s[i*HALO_W + j], acc);
        }
        float wc = sw[c];
        float lg = lgu[c*HW];
        m[c] = fmaf(wc, acc - lg, lg);   // (1-wc)*lg + wc*acc
    }

    // ---- softmax over classes (registers) + store ----
    float* po = pout + b*CC*HW + pix;
    if (do_sm) {
        float mx = m[0];
        #pragma unroll
        for (int c = 1; c < CC; c++) mx = fmaxf(mx, m[c]);
        float s = 0.f;
        #pragma unroll
        for (int c = 0; c < CC; c++) { m[c] = __expf(m[c] - mx); s += m[c]; }
        float inv = 1.f / s;
        #pragma unroll
        for (int c = 0; c < CC; c++) m[c] *= inv;
    }
    #pragma unroll
    for (int c = 0; c < CC; c++)
        po[c*HW] = m[c];
}

// ---------------------------------------------------------------------------
extern "C" void kernel_launch(void* const* d_in, const int* in_sizes, int n_in,
                              void* d_out, int out_size) {
    const float* unary  = nullptr;   // 2*21*256*256 = 2752512
    const float* img    = nullptr;   // 2*3*256*256  = 393216
    const float* weight = nullptr;   // 21
    for (int i = 0; i < n_in; i++) {
        if (in_sizes[i] == BB*CC*HW)      unary  = (const float*)d_in[i];
        else if (in_sizes[i] == BB*3*HW)  img    = (const float*)d_in[i];
        else if (in_sizes[i] == CC)       weight = (const float*)d_in[i];
        // num_iter (1 elem) fixed at 5 by problem setup.
    }
    float* out = (float*)d_out;

    dim3 blk(TX, TY);
    dim3 grd(WW/TX, HH/TY, BB);           // 8 x 32 x 2 = 512 blocks

    gauss_kernel<<<grd, blk>>>(img);
    lsm_kernel<<<(BB*HW + 255)/256, 256>>>(unary);
    for (int it = 0; it < 5; it++)
        iter_kernel<<<grd, blk>>>(weight, out, it);
}

// round 7
// speedup vs baseline: 2.4583x; 1.2868x over previous
#include <cuda_runtime.h>

#define HH 256
#define WW 256
#define BB 2
#define CC 21
#define KF 7
#define SPAN 3
#define KK 49
#define HW (HH*WW)

// ---- setup kernels tile (unchanged, proven) ----
#define TX 32
#define TY 8
#define HALO_W (TX + 2*SPAN)   // 38
#define HALO_H (TY + 2*SPAN)   // 14
#define HALO_N (HALO_W * HALO_H)  // 532

// ---- iter kernel tile: 64 wide x 4 tall, 2 px/thread horizontally ----
#define T2W 64
#define T2H 4
#define NTHR2 128              // 32 x 4
#define H2W 72                 // halo row width 70, padded to 72 (8B align)
#define H2H (T2H + 2*SPAN)     // 10
#define H2N (H2W * H2H)        // 720
#define SMEM_DYN (CC * H2N * 4)  // 60480 bytes

// Scratch (no allocations allowed -> __device__ globals)
__device__ float g_gauss[BB*KK*HW];       // [b][k][h][w]
__device__ float g_lgu[BB*CC*HW];         // log-softmax(unary)
__device__ float g_pred[2][BB*CC*HW];     // ping-pong prediction buffers

// ---------------------------------------------------------------------------
// Kernel A: pairwise Gaussian weights (pos + color), computed once.
// ---------------------------------------------------------------------------
__global__ __launch_bounds__(256) void gauss_kernel(const float* __restrict__ img) {
    __shared__ float simg[3][HALO_H][HALO_W];
    const int b  = blockIdx.z;
    const int tx = threadIdx.x, ty = threadIdx.y;
    const int tid = ty * TX + tx;
    const int h0 = blockIdx.y * TY, w0 = blockIdx.x * TX;

    for (int idx = tid; idx < 3 * HALO_N; idx += 256) {
        int ch = idx / HALO_N;
        int rem = idx % HALO_N;
        int r = rem / HALO_W, c = rem % HALO_W;
        int gh = h0 - SPAN + r, gw = w0 - SPAN + c;
        float v = 0.f;
        if (gh >= 0 && gh < HH && gw >= 0 && gw < WW)
            v = img[(b*3 + ch)*HW + gh*WW + gw] * (1.f/13.f);
        simg[ch][r][c] = v;
    }
    __syncthreads();

    const int h = h0 + ty, w = w0 + tx;
    const float c0 = simg[0][ty+SPAN][tx+SPAN];
    const float c1 = simg[1][ty+SPAN][tx+SPAN];
    const float c2 = simg[2][ty+SPAN][tx+SPAN];

    #pragma unroll
    for (int i = 0; i < KF; i++) {
        #pragma unroll
        for (int j = 0; j < KF; j++) {
            const int k = i*KF + j;
            const int dh = i - SPAN, dw = j - SPAN;
            const int nh = h + dh, nw = w + dw;
            float g = 0.f;
            if (nh >= 0 && nh < HH && nw >= 0 && nw < WW) {
                float d0 = simg[0][ty+i][tx+j] - c0;
                float d1 = simg[1][ty+i][tx+j] - c1;
                float d2 = simg[2][ty+i][tx+j] - c2;
                float col = __expf(-0.5f*(d0*d0 + d1*d1 + d2*d2));
                float pos = __expf(-(float)(dh*dh + dw*dw) * (0.5f/9.f));
                g = 3.f*pos + 10.f*col;
            }
            g_gauss[(b*KK + k)*HW + h*WW + w] = g;
        }
    }
}

// ---------------------------------------------------------------------------
// Kernel B: log_softmax over classes; seeds prediction buffer 0.
// ---------------------------------------------------------------------------
__global__ __launch_bounds__(256) void lsm_kernel(const float* __restrict__ unary) {
    int idx = blockIdx.x * blockDim.x + threadIdx.x;   // over B*HW
    if (idx >= BB*HW) return;
    int b = idx / HW, p = idx % HW;
    const float* u = unary + b*CC*HW + p;

    float v[CC];
    float mx = -1e30f;
    #pragma unroll
    for (int c = 0; c < CC; c++) { v[c] = u[c*HW]; mx = fmaxf(mx, v[c]); }
    float s = 0.f;
    #pragma unroll
    for (int c = 0; c < CC; c++) s += __expf(v[c] - mx);
    float lse = mx + __logf(s);
    #pragma unroll
    for (int c = 0; c < CC; c++) {
        float lg = v[c] - lse;
        g_lgu[(b*CC + c)*HW + p]      = lg;
        g_pred[0][(b*CC + c)*HW + p]  = lg;
    }
}

// ---------------------------------------------------------------------------
// Kernel C: one mean-field iteration — 2 pixels/thread, float2 smem reads.
//   * tile 64x4, 128 threads; thread (tx,ty) owns pixels (h0+ty, w0+2tx+{0,1})
//   * all 21 class halo tiles staged in DYNAMIC smem (60.5 KB), one barrier
//   * row-outer / class-inner: per filter row, the two pixels' tap windows
//     union to 8 consecutive floats -> 4 aligned LDS.64 feed 14 FMAs
//     (0.875 crossbar-cyc/px/class vs 1.53 for scalar 1px/thread)
//   * gaussian: 7 float2 pairs per row, prefetched one row ahead (L2-hot)
//   * acc0/acc1[21] register-resident; softmax in registers
// ---------------------------------------------------------------------------
extern __shared__ float sp2[];   // [CC][H2N]

__global__ __launch_bounds__(NTHR2, 3) void iter2_kernel(const float* __restrict__ wt,
                                                         float* __restrict__ dout,
                                                         int it) {
    __shared__ float sw[CC];

    const float* __restrict__ pin = g_pred[it & 1];
    float* __restrict__ pout = (it == 4) ? dout : g_pred[(it + 1) & 1];
    const int do_sm = (it != 4);

    const int b  = blockIdx.z;
    const int tx = threadIdx.x, ty = threadIdx.y;     // 32 x 4
    const int tid = ty * 32 + tx;
    const int h0 = blockIdx.y * T2H, w0 = blockIdx.x * T2W;
    const int h = h0 + ty, w = w0 + 2*tx;
    const int pix = h*WW + w;                         // even -> float2-aligned

    if (tid < CC) sw[tid] = wt[tid];

    // ---- halo-load plan: 720 entries, 128 threads -> 6 slots (last partial)
    int go[6]; float okf[6];
    #pragma unroll
    for (int s = 0; s < 6; s++) {
        int idx = tid + s*NTHR2;
        int r = idx / H2W, c = idx % H2W;
        int gh = h0 - SPAN + r, gw = w0 - SPAN + c;
        bool ok = (idx < H2N) && (gh >= 0) && (gh < HH) && (gw >= 0) && (gw < WW);
        okf[s] = ok ? 1.f : 0.f;
        go[s] = min(max(gh,0),HH-1)*WW + min(max(gw,0),WW-1);
    }

    // ---- stage all 21 class halo tiles (big LDG batch, huge MLP) ----
    {
        const float* pc = pin + b*CC*HW;
        #pragma unroll
        for (int c = 0; c < CC; c++, pc += HW) {
            float* d = sp2 + c*H2N;
            #pragma unroll
            for (int s = 0; s < 5; s++)
                d[tid + s*NTHR2] = pc[go[s]] * okf[s];
            if (tid < H2N - 5*NTHR2)                  // tid < 80
                d[tid + 5*NTHR2] = pc[go[5]] * okf[5];
        }
    }

    // ---- prefetch gaussian row 0 (7 float2 pairs) ----
    const float* gg = g_gauss + b*KK*HW + pix;
    float2 gc[KF], gn[KF];
    #pragma unroll
    for (int j = 0; j < KF; j++)
        gc[j] = *(const float2*)(gg + j*HW);

    __syncthreads();   // the ONLY barrier

    float acc0[CC], acc1[CC];
    #pragma unroll
    for (int c = 0; c < CC; c++) { acc0[c] = 0.f; acc1[c] = 0.f; }

    // ---- row-outer / class-inner compute ----
    #pragma unroll 1
    for (int i = 0; i < KF; i++) {
        // prefetch next gaussian row (row 6 reloaded harmlessly on last iter)
        const int inx = (i < KF-1) ? (i+1) : i;
        #pragma unroll
        for (int j = 0; j < KF; j++)
            gn[j] = *(const float2*)(gg + (inx*KF + j)*HW);

        const float* rowbase = sp2 + (ty + i)*H2W + 2*tx;
        #pragma unroll
        for (int c = 0; c < CC; c++) {
            const float2* e2 = (const float2*)(rowbase + c*H2N);
            float2 p01 = e2[0], p23 = e2[1], p45 = e2[2], p67 = e2[3];
            float e0 = p01.x, e1 = p01.y, e2v = p23.x, e3 = p23.y;
            float e4 = p45.x, e5 = p45.y, e6 = p67.x, e7 = p67.y;
            acc0[c] = fmaf(gc[0].x, e0, acc0[c]);  acc1[c] = fmaf(gc[0].y, e1, acc1[c]);
            acc0[c] = fmaf(gc[1].x, e1, acc0[c]);  acc1[c] = fmaf(gc[1].y, e2v, acc1[c]);
            acc0[c] = fmaf(gc[2].x, e2v, acc0[c]); acc1[c] = fmaf(gc[2].y, e3, acc1[c]);
            acc0[c] = fmaf(gc[3].x, e3, acc0[c]);  acc1[c] = fmaf(gc[3].y, e4, acc1[c]);
            acc0[c] = fmaf(gc[4].x, e4, acc0[c]);  acc1[c] = fmaf(gc[4].y, e5, acc1[c]);
            acc0[c] = fmaf(gc[5].x, e5, acc0[c]);  acc1[c] = fmaf(gc[5].y, e6, acc1[c]);
            acc0[c] = fmaf(gc[6].x, e6, acc0[c]);  acc1[c] = fmaf(gc[6].y, e7, acc1[c]);
        }
        #pragma unroll
        for (int j = 0; j < KF; j++) gc[j] = gn[j];
    }

    // ---- blend with log-unary ----
    const float* lgu = g_lgu + b*CC*HW + pix;
    #pragma unroll
    for (int c = 0; c < CC; c++) {
        float wc = sw[c];
        float2 lg = *(const float2*)(lgu + c*HW);
        acc0[c] = fmaf(wc, acc0[c] - lg.x, lg.x);
        acc1[c] = fmaf(wc, acc1[c] - lg.y, lg.y);
    }

    // ---- softmax over classes (registers) + store ----
    if (do_sm) {
        float mx0 = acc0[0], mx1 = acc1[0];
        #pragma unroll
        for (int c = 1; c < CC; c++) { mx0 = fmaxf(mx0, acc0[c]); mx1 = fmaxf(mx1, acc1[c]); }
        float s0 = 0.f, s1 = 0.f;
        #pragma unroll
        for (int c = 0; c < CC; c++) {
            acc0[c] = __expf(acc0[c] - mx0); s0 += acc0[c];
            acc1[c] = __expf(acc1[c] - mx1); s1 += acc1[c];
        }
        float i0 = 1.f / s0, i1 = 1.f / s1;
        #pragma unroll
        for (int c = 0; c < CC; c++) { acc0[c] *= i0; acc1[c] *= i1; }
    }
    float* po = pout + b*CC*HW + pix;
    #pragma unroll
    for (int c = 0; c < CC; c++)
        *(float2*)(po + c*HW) = make_float2(acc0[c], acc1[c]);
}

// ---------------------------------------------------------------------------
extern "C" void kernel_launch(void* const* d_in, const int* in_sizes, int n_in,
                              void* d_out, int out_size) {
    const float* unary  = nullptr;   // 2*21*256*256 = 2752512
    const float* img    = nullptr;   // 2*3*256*256  = 393216
    const float* weight = nullptr;   // 21
    for (int i = 0; i < n_in; i++) {
        if (in_sizes[i] == BB*CC*HW)      unary  = (const float*)d_in[i];
        else if (in_sizes[i] == BB*3*HW)  img    = (const float*)d_in[i];
        else if (in_sizes[i] == CC)       weight = (const float*)d_in[i];
        // num_iter (1 elem) fixed at 5 by problem setup.
    }
    float* out = (float*)d_out;

    // allow 60.5 KB dynamic smem (host-side attribute set; not an allocation,
    // not a stream op -> graph-capture safe; idempotent)
    cudaFuncSetAttribute(iter2_kernel,
                         cudaFuncAttributeMaxDynamicSharedMemorySize, SMEM_DYN);

    dim3 blkA(TX, TY);
    dim3 grdA(WW/TX, HH/TY, BB);          // 8 x 32 x 2
    gauss_kernel<<<grdA, blkA>>>(img);
    lsm_kernel<<<(BB*HW + 255)/256, 256>>>(unary);

    dim3 blkC(32, 4);
    dim3 grdC(WW/T2W, HH/T2H, BB);        // 4 x 64 x 2 = 512 blocks
    for (int it = 0; it < 5; it++)
        iter2_kernel<<<grdC, blkC, SMEM_DYN>>>(weight, out, it);
}

// round 10
// speedup vs baseline: 2.5398x; 1.0332x over previous
#include <cuda_runtime.h>

#define HH 256
#define WW 256
#define BB 2
#define CC 21
#define KF 7
#define SPAN 3
#define KK 49
#define HW (HH*WW)

// ---- setup kernels tile (unchanged, proven) ----
#define TX 32
#define TY 8
#define HALO_W (TX + 2*SPAN)   // 38
#define HALO_H (TY + 2*SPAN)   // 14
#define HALO_N (HALO_W * HALO_H)  // 532

// ---- iter kernel tile: 64 wide x 4 tall, 2 px/thread horizontally ----
#define T2W 64
#define T2H 4
#define NTHR2 128              // 32 x 4
#define H2W 72                 // halo row width 70, padded to 72 (8B align)
#define H2H (T2H + 2*SPAN)     // 10
#define H2N (H2W * H2H)        // 720
#define NCMAX 11               // max classes staged at once
#define SMEM_DYN (NCMAX * H2N * 4)   // 31680 bytes

// Scratch (no allocations allowed -> __device__ globals)
__device__ float g_gauss[BB*KK*HW];       // [b][k][h][w]
__device__ float g_lgu[BB*CC*HW];         // log-softmax(unary)
__device__ float g_pred[2][BB*CC*HW];     // ping-pong prediction buffers

// ---------------------------------------------------------------------------
// Kernel A: pairwise Gaussian weights (pos + color), computed once.
// ---------------------------------------------------------------------------
__global__ __launch_bounds__(256) void gauss_kernel(const float* __restrict__ img) {
    __shared__ float simg[3][HALO_H][HALO_W];
    const int b  = blockIdx.z;
    const int tx = threadIdx.x, ty = threadIdx.y;
    const int tid = ty * TX + tx;
    const int h0 = blockIdx.y * TY, w0 = blockIdx.x * TX;

    for (int idx = tid; idx < 3 * HALO_N; idx += 256) {
        int ch = idx / HALO_N;
        int rem = idx % HALO_N;
        int r = rem / HALO_W, c = rem % HALO_W;
        int gh = h0 - SPAN + r, gw = w0 - SPAN + c;
        float v = 0.f;
        if (gh >= 0 && gh < HH && gw >= 0 && gw < WW)
            v = img[(b*3 + ch)*HW + gh*WW + gw] * (1.f/13.f);
        simg[ch][r][c] = v;
    }
    __syncthreads();

    const int h = h0 + ty, w = w0 + tx;
    const float c0 = simg[0][ty+SPAN][tx+SPAN];
    const float c1 = simg[1][ty+SPAN][tx+SPAN];
    const float c2 = simg[2][ty+SPAN][tx+SPAN];

    #pragma unroll
    for (int i = 0; i < KF; i++) {
        #pragma unroll
        for (int j = 0; j < KF; j++) {
            const int k = i*KF + j;
            const int dh = i - SPAN, dw = j - SPAN;
            const int nh = h + dh, nw = w + dw;
            float g = 0.f;
            if (nh >= 0 && nh < HH && nw >= 0 && nw < WW) {
                float d0 = simg[0][ty+i][tx+j] - c0;
                float d1 = simg[1][ty+i][tx+j] - c1;
                float d2 = simg[2][ty+i][tx+j] - c2;
                float col = __expf(-0.5f*(d0*d0 + d1*d1 + d2*d2));
                float pos = __expf(-(float)(dh*dh + dw*dw) * (0.5f/9.f));
                g = 3.f*pos + 10.f*col;
            }
            g_gauss[(b*KK + k)*HW + h*WW + w] = g;
        }
    }
}

// ---------------------------------------------------------------------------
// Kernel B: log_softmax over classes; seeds prediction buffer 0.
// ---------------------------------------------------------------------------
__global__ __launch_bounds__(256) void lsm_kernel(const float* __restrict__ unary) {
    int idx = blockIdx.x * blockDim.x + threadIdx.x;   // over B*HW
    if (idx >= BB*HW) return;
    int b = idx / HW, p = idx % HW;
    const float* u = unary + b*CC*HW + p;

    float v[CC];
    float mx = -1e30f;
    #pragma unroll
    for (int c = 0; c < CC; c++) { v[c] = u[c*HW]; mx = fmaxf(mx, v[c]); }
    float s = 0.f;
    #pragma unroll
    for (int c = 0; c < CC; c++) s += __expf(v[c] - mx);
    float lse = mx + __logf(s);
    #pragma unroll
    for (int c = 0; c < CC; c++) {
        float lg = v[c] - lse;
        g_lgu[(b*CC + c)*HW + p]      = lg;
        g_pred[0][(b*CC + c)*HW + p]  = lg;
    }
}

// ---------------------------------------------------------------------------
// Kernel C: one mean-field iteration — 2 px/thread, classes in 2 chunks.
//   * chunked staging (11 + 10 classes) -> 31.7 KB dynamic smem
//   * __launch_bounds__(128,4): regs<=128 -> 4 blocks/SM = 16 warps (2x R7)
//   * per filter row: 4 aligned LDS.64 feed 14 FMAs for 2 adjacent pixels
//   * gaussian rows loaded per (chunk,row) from L2-hot global (no prefetch
//     registers; latency covered by doubled warp count)
// ---------------------------------------------------------------------------
extern __shared__ float sp2[];   // [NCMAX][H2N]

template<int C0, int NC>
__device__ __forceinline__ void crf_chunk(const float* __restrict__ pin_b,
                                          const float* __restrict__ gg,
                                          int tid, int ty, int tx,
                                          const int* go, const float* okf,
                                          float* acc0, float* acc1) {
    // ---- stage NC class halo tiles ----
    const float* pc = pin_b + C0*HW;
    #pragma unroll
    for (int c = 0; c < NC; c++, pc += HW) {
        float* d = sp2 + c*H2N;
        #pragma unroll
        for (int s = 0; s < 5; s++)
            d[tid + s*NTHR2] = pc[go[s]] * okf[s];
        if (tid < H2N - 5*NTHR2)                  // tid < 80
            d[tid + 5*NTHR2] = pc[go[5]] * okf[5];
    }
    __syncthreads();

    // ---- row-outer / class-inner compute ----
    #pragma unroll 1
    for (int i = 0; i < KF; i++) {
        float2 gc[KF];
        #pragma unroll
        for (int j = 0; j < KF; j++)
            gc[j] = *(const float2*)(gg + (i*KF + j)*HW);

        const float* rowbase = sp2 + (ty + i)*H2W + 2*tx;
        #pragma unroll
        for (int c = 0; c < NC; c++) {
            const float2* e2 = (const float2*)(rowbase + c*H2N);
            float2 p01 = e2[0], p23 = e2[1], p45 = e2[2], p67 = e2[3];
            float e0 = p01.x, e1 = p01.y, e2v = p23.x, e3 = p23.y;
            float e4 = p45.x, e5 = p45.y, e6 = p67.x, e7 = p67.y;
            float a0 = acc0[C0+c], a1 = acc1[C0+c];
            a0 = fmaf(gc[0].x, e0, a0);   a1 = fmaf(gc[0].y, e1, a1);
            a0 = fmaf(gc[1].x, e1, a0);   a1 = fmaf(gc[1].y, e2v, a1);
            a0 = fmaf(gc[2].x, e2v, a0);  a1 = fmaf(gc[2].y, e3, a1);
            a0 = fmaf(gc[3].x, e3, a0);   a1 = fmaf(gc[3].y, e4, a1);
            a0 = fmaf(gc[4].x, e4, a0);   a1 = fmaf(gc[4].y, e5, a1);
            a0 = fmaf(gc[5].x, e5, a0);   a1 = fmaf(gc[5].y, e6, a1);
            a0 = fmaf(gc[6].x, e6, a0);   a1 = fmaf(gc[6].y, e7, a1);
            acc0[C0+c] = a0; acc1[C0+c] = a1;
        }
    }
    __syncthreads();   // smem reused by next chunk
}

__global__ __launch_bounds__(NTHR2, 4) void iter2_kernel(const float* __restrict__ wt,
                                                         float* __restrict__ dout,
                                                         int it) {
    __shared__ float sw[CC];

    const float* __restrict__ pin = g_pred[it & 1];
    float* __restrict__ pout = (it == 4) ? dout : g_pred[(it + 1) & 1];
    const int do_sm = (it != 4);

    const int b  = blockIdx.z;
    const int tx = threadIdx.x, ty = threadIdx.y;     // 32 x 4
    const int tid = ty * 32 + tx;
    const int h0 = blockIdx.y * T2H, w0 = blockIdx.x * T2W;
    const int h = h0 + ty, w = w0 + 2*tx;
    const int pix = h*WW + w;                         // even -> float2-aligned

    if (tid < CC) sw[tid] = wt[tid];

    // ---- halo-load plan: 720 entries, 128 threads -> 6 slots (last partial)
    int go[6]; float okf[6];
    #pragma unroll
    for (int s = 0; s < 6; s++) {
        int idx = tid + s*NTHR2;
        int r = idx / H2W, c = idx % H2W;
        int gh = h0 - SPAN + r, gw = w0 - SPAN + c;
        bool ok = (idx < H2N) && (gh >= 0) && (gh < HH) && (gw >= 0) && (gw < WW);
        okf[s] = ok ? 1.f : 0.f;
        go[s] = min(max(gh,0),HH-1)*WW + min(max(gw,0),WW-1);
    }

    const float* pin_b = pin + b*CC*HW;
    const float* gg = g_gauss + b*KK*HW + pix;

    float acc0[CC], acc1[CC];
    #pragma unroll
    for (int c = 0; c < CC; c++) { acc0[c] = 0.f; acc1[c] = 0.f; }

    crf_chunk<0, 11>(pin_b, gg, tid, ty, tx, go, okf, acc0, acc1);
    crf_chunk<11, 10>(pin_b, gg, tid, ty, tx, go, okf, acc0, acc1);

    // ---- blend with log-unary ----
    const float* lgu = g_lgu + b*CC*HW + pix;
    #pragma unroll
    for (int c = 0; c < CC; c++) {
        float wc = sw[c];
        float2 lg = *(const float2*)(lgu + c*HW);
        acc0[c] = fmaf(wc, acc0[c] - lg.x, lg.x);
        acc1[c] = fmaf(wc, acc1[c] - lg.y, lg.y);
    }

    // ---- softmax over classes (registers) + store ----
    if (do_sm) {
        float mx0 = acc0[0], mx1 = acc1[0];
        #pragma unroll
        for (int c = 1; c < CC; c++) { mx0 = fmaxf(mx0, acc0[c]); mx1 = fmaxf(mx1, acc1[c]); }
        float s0 = 0.f, s1 = 0.f;
        #pragma unroll
        for (int c = 0; c < CC; c++) {
            acc0[c] = __expf(acc0[c] - mx0); s0 += acc0[c];
            acc1[c] = __expf(acc1[c] - mx1); s1 += acc1[c];
        }
        float i0 = 1.f / s0, i1 = 1.f / s1;
        #pragma unroll
        for (int c = 0; c < CC; c++) { acc0[c] *= i0; acc1[c] *= i1; }
    }
    float* po = pout + b*CC*HW + pix;
    #pragma unroll
    for (int c = 0; c < CC; c++)
        *(float2*)(po + c*HW) = make_float2(acc0[c], acc1[c]);
}

// ---------------------------------------------------------------------------
extern "C" void kernel_launch(void* const* d_in, const int* in_sizes, int n_in,
                              void* d_out, int out_size) {
    const float* unary  = nullptr;   // 2*21*256*256 = 2752512
    const float* img    = nullptr;   // 2*3*256*256  = 393216
    const float* weight = nullptr;   // 21
    for (int i = 0; i < n_in; i++) {
        if (in_sizes[i] == BB*CC*HW)      unary  = (const float*)d_in[i];
        else if (in_sizes[i] == BB*3*HW)  img    = (const float*)d_in[i];
        else if (in_sizes[i] == CC)       weight = (const float*)d_in[i];
        // num_iter (1 elem) fixed at 5 by problem setup.
    }
    float* out = (float*)d_out;

    // allow 31.7 KB dynamic smem (host attribute; not an allocation; capture-safe)
    cudaFuncSetAttribute(iter2_kernel,
                         cudaFuncAttributeMaxDynamicSharedMemorySize, SMEM_DYN);

    dim3 blkA(TX, TY);
    dim3 grdA(WW/TX, HH/TY, BB);          // 8 x 32 x 2
    gauss_kernel<<<grdA, blkA>>>(img);
    lsm_kernel<<<(BB*HW + 255)/256, 256>>>(unary);

    dim3 blkC(32, 4);
    dim3 grdC(WW/T2W, HH/T2H, BB);        // 4 x 64 x 2 = 512 blocks
    for (int it = 0; it < 5; it++)
        iter2_kernel<<<grdC, blkC, SMEM_DYN>>>(weight, out, it);
}

// round 14
// speedup vs baseline: 2.5830x; 1.0170x over previous
#include <cuda_runtime.h>
#include <cuda_fp16.h>

#define HH 256
#define WW 256
#define BB 2
#define CC 21
#define KF 7
#define SPAN 3
#define KK 49
#define HW (HH*WW)
#define HWH (HW/2)             // half2 pixel-pairs per (b,k) plane

// ---- gauss kernel tile: 64 wide x 8 tall, 2 px/thread ----
#define GTW 64
#define GTH 8
#define GHW 70                 // 64 + 6
#define GHH 14                 // 8 + 6

// ---- iter kernel tile: 64 wide x 4 tall, 2 px/thread horizontally ----
#define T2W 64
#define T2H 4
#define NTHR2 128              // 32 x 4
#define H2W 72                 // halo row width 70, padded to 72 (8B align)
#define H2H (T2H + 2*SPAN)     // 10
#define H2N (H2W * H2H)        // 720
#define NCMAX 11               // max classes staged at once
#define SMEM_DYN (NCMAX * H2N * 4)   // 31680 bytes

// Scratch (no allocations allowed -> __device__ globals)
__device__ __half2 g_gauss_h[BB*KK*HWH]; // [b][k][pixel-pair] fp16x2
__device__ float g_lgu[BB*CC*HW];        // log-softmax(unary)
__device__ float g_pred[2][BB*CC*HW];    // ping-pong prediction buffers

// ---------------------------------------------------------------------------
// Kernel A: pairwise Gaussian weights (pos + color), 2 px/thread, fp16x2 out.
// ---------------------------------------------------------------------------
__global__ __launch_bounds__(256) void gauss_kernel(const float* __restrict__ img) {
    __shared__ float simg[3][GHH][GHW];
    const int b  = blockIdx.z;
    const int tx = threadIdx.x, ty = threadIdx.y;   // 32 x 8
    const int tid = ty * 32 + tx;
    const int h0 = blockIdx.y * GTH, w0 = blockIdx.x * GTW;

    for (int idx = tid; idx < 3 * GHH * GHW; idx += 256) {
        int ch = idx / (GHH * GHW);
        int rem = idx % (GHH * GHW);
        int r = rem / GHW, c = rem % GHW;
        int gh = h0 - SPAN + r, gw = w0 - SPAN + c;
        float v = 0.f;
        if (gh >= 0 && gh < HH && gw >= 0 && gw < WW)
            v = img[(b*3 + ch)*HW + gh*WW + gw] * (1.f/13.f);
        simg[ch][r][c] = v;
    }
    __syncthreads();

    const int h = h0 + ty;
    const int w = w0 + 2*tx;
    const int sx = 2*tx;   // halo col of px0 center minus SPAN
    const float a0 = simg[0][ty+SPAN][sx+SPAN],  b0v = simg[1][ty+SPAN][sx+SPAN],  c0v = simg[2][ty+SPAN][sx+SPAN];
    const float a1 = simg[0][ty+SPAN][sx+1+SPAN], b1v = simg[1][ty+SPAN][sx+1+SPAN], c1v = simg[2][ty+SPAN][sx+1+SPAN];

    #pragma unroll
    for (int i = 0; i < KF; i++) {
        #pragma unroll
        for (int j = 0; j < KF; j++) {
            const int k = i*KF + j;
            const int dh = i - SPAN, dw = j - SPAN;
            const int nh = h + dh;
            const float pos = __expf(-(float)(dh*dh + dw*dw) * (0.5f/9.f));
            float g0 = 0.f, g1 = 0.f;
            if (nh >= 0 && nh < HH) {
                int nw0 = w + dw, nw1 = w + 1 + dw;
                if (nw0 >= 0 && nw0 < WW) {
                    float d0 = simg[0][ty+i][sx+j]   - a0;
                    float d1 = simg[1][ty+i][sx+j]   - b0v;
                    float d2 = simg[2][ty+i][sx+j]   - c0v;
                    g0 = 3.f*pos + 10.f*__expf(-0.5f*(d0*d0 + d1*d1 + d2*d2));
                }
                if (nw1 >= 0 && nw1 < WW) {
                    float d0 = simg[0][ty+i][sx+1+j] - a1;
                    float d1 = simg[1][ty+i][sx+1+j] - b1v;
                    float d2 = simg[2][ty+i][sx+1+j] - c1v;
                    g1 = 3.f*pos + 10.f*__expf(-0.5f*(d0*d0 + d1*d1 + d2*d2));
                }
            }
            g_gauss_h[(b*KK + k)*HWH + h*(WW/2) + (w>>1)] = __floats2half2_rn(g0, g1);
        }
    }
}

// ---------------------------------------------------------------------------
// Kernel B: log_softmax over classes; seeds prediction buffer 0.
// ---------------------------------------------------------------------------
__global__ __launch_bounds__(256) void lsm_kernel(const float* __restrict__ unary) {
    int idx = blockIdx.x * blockDim.x + threadIdx.x;   // over B*HW
    if (idx >= BB*HW) return;
    int b = idx / HW, p = idx % HW;
    const float* u = unary + b*CC*HW + p;

    float v[CC];
    float mx = -1e30f;
    #pragma unroll
    for (int c = 0; c < CC; c++) { v[c] = u[c*HW]; mx = fmaxf(mx, v[c]); }
    float s = 0.f;
    #pragma unroll
    for (int c = 0; c < CC; c++) s += __expf(v[c] - mx);
    float lse = mx + __logf(s);
    #pragma unroll
    for (int c = 0; c < CC; c++) {
        float lg = v[c] - lse;
        g_lgu[(b*CC + c)*HW + p]      = lg;
        g_pred[0][(b*CC + c)*HW + p]  = lg;
    }
}

// ---------------------------------------------------------------------------
// Kernel C: one mean-field iteration — 2 px/thread, classes in 2 chunks,
// fp16x2 gaussian with next-row prefetch.
// ---------------------------------------------------------------------------
extern __shared__ float sp2[];   // [NCMAX][H2N]

template<int C0, int NC>
__device__ __forceinline__ void crf_chunk(const float* __restrict__ pin_b,
                                          const unsigned int* __restrict__ gg,
                                          int tid, int ty, int tx,
                                          int h0, int w0,
                                          float* acc0, float* acc1) {
    // ---- stage NC class halo tiles; plan recomputed per slot (reg diet) ----
    const float* pc = pin_b + C0*HW;
    #pragma unroll
    for (int s = 0; s < 6; s++) {
        int idx = tid + s*NTHR2;
        if (s < 5 || idx < H2N) {
            int r = idx / H2W, c = idx % H2W;
            int gh = h0 - SPAN + r, gw = w0 - SPAN + c;
            float okf = (gh >= 0 && gh < HH && gw >= 0 && gw < WW) ? 1.f : 0.f;
            int go = min(max(gh,0),HH-1)*WW + min(max(gw,0),WW-1);
            const float* p2 = pc;
            #pragma unroll
            for (int c2 = 0; c2 < NC; c2++, p2 += HW)
                sp2[c2*H2N + idx] = p2[go] * okf;
        }
    }
    __syncthreads();

    // ---- gaussian row 0 prefetch (raw half2 words) ----
    unsigned int graw[KF];
    #pragma unroll
    for (int j = 0; j < KF; j++) graw[j] = gg[j*HWH];

    // ---- row-outer / class-inner compute ----
    #pragma unroll 1
    for (int i = 0; i < KF; i++) {
        float2 gc[KF];
        #pragma unroll
        for (int j = 0; j < KF; j++)
            gc[j] = __half22float2(*reinterpret_cast<const __half2*>(&graw[j]));
        if (i < KF-1) {
            #pragma unroll
            for (int j = 0; j < KF; j++)
                graw[j] = gg[((i+1)*KF + j)*HWH];
        }

        const float* rowbase = sp2 + (ty + i)*H2W + 2*tx;
        #pragma unroll
        for (int c = 0; c < NC; c++) {
            const float2* e2 = (const float2*)(rowbase + c*H2N);
            float2 p01 = e2[0], p23 = e2[1], p45 = e2[2], p67 = e2[3];
            float e0 = p01.x, e1 = p01.y, e2v = p23.x, e3 = p23.y;
            float e4 = p45.x, e5 = p45.y, e6 = p67.x, e7 = p67.y;
            float a0 = acc0[C0+c], a1 = acc1[C0+c];
            a0 = fmaf(gc[0].x, e0, a0);   a1 = fmaf(gc[0].y, e1, a1);
            a0 = fmaf(gc[1].x, e1, a0);   a1 = fmaf(gc[1].y, e2v, a1);
            a0 = fmaf(gc[2].x, e2v, a0);  a1 = fmaf(gc[2].y, e3, a1);
            a0 = fmaf(gc[3].x, e3, a0);   a1 = fmaf(gc[3].y, e4, a1);
            a0 = fmaf(gc[4].x, e4, a0);   a1 = fmaf(gc[4].y, e5, a1);
            a0 = fmaf(gc[5].x, e5, a0);   a1 = fmaf(gc[5].y, e6, a1);
            a0 = fmaf(gc[6].x, e6, a0);   a1 = fmaf(gc[6].y, e7, a1);
            acc0[C0+c] = a0; acc1[C0+c] = a1;
        }
    }
    __syncthreads();   // smem reused by next chunk
}

__global__ __launch_bounds__(NTHR2, 4) void iter2_kernel(const float* __restrict__ wt,
                                                         float* __restrict__ dout,
                                                         int it) {
    __shared__ float sw[CC];

    const float* __restrict__ pin = g_pred[it & 1];
    float* __restrict__ pout = (it == 4) ? dout : g_pred[(it + 1) & 1];
    const int do_sm = (it != 4);

    const int b  = blockIdx.z;
    const int tx = threadIdx.x, ty = threadIdx.y;     // 32 x 4
    const int tid = ty * 32 + tx;
    const int h0 = blockIdx.y * T2H, w0 = blockIdx.x * T2W;
    const int h = h0 + ty, w = w0 + 2*tx;
    const int pix = h*WW + w;                         // even -> float2-aligned

    if (tid < CC) sw[tid] = wt[tid];

    const float* pin_b = pin + b*CC*HW;
    const unsigned int* gg = reinterpret_cast<const unsigned int*>(g_gauss_h)
                           + b*KK*HWH + h*(WW/2) + (w>>1);

    float acc0[CC], acc1[CC];
    #pragma unroll
    for (int c = 0; c < CC; c++) { acc0[c] = 0.f; acc1[c] = 0.f; }

    crf_chunk<0, 11>(pin_b, gg, tid, ty, tx, h0, w0, acc0, acc1);
    crf_chunk<11, 10>(pin_b, gg, tid, ty, tx, h0, w0, acc0, acc1);

    // ---- blend with log-unary ----
    const float* lgu = g_lgu + b*CC*HW + pix;
    #pragma unroll
    for (int c = 0; c < CC; c++) {
        float wc = sw[c];
        float2 lg = *(const float2*)(lgu + c*HW);
        acc0[c] = fmaf(wc, acc0[c] - lg.x, lg.x);
        acc1[c] = fmaf(wc, acc1[c] - lg.y, lg.y);
    }

    // ---- softmax over classes (registers) + store ----
    if (do_sm) {
        float mx0 = acc0[0], mx1 = acc1[0];
        #pragma unroll
        for (int c = 1; c < CC; c++) { mx0 = fmaxf(mx0, acc0[c]); mx1 = fmaxf(mx1, acc1[c]); }
        float s0 = 0.f, s1 = 0.f;
        #pragma unroll
        for (int c = 0; c < CC; c++) {
            acc0[c] = __expf(acc0[c] - mx0); s0 += acc0[c];
            acc1[c] = __expf(acc1[c] - mx1); s1 += acc1[c];
        }
        float i0 = 1.f / s0, i1 = 1.f / s1;
        #pragma unroll
        for (int c = 0; c < CC; c++) { acc0[c] *= i0; acc1[c] *= i1; }
    }
    float* po = pout + b*CC*HW + pix;
    #pragma unroll
    for (int c = 0; c < CC; c++)
        *(float2*)(po + c*HW) = make_float2(acc0[c], acc1[c]);
}

// ---------------------------------------------------------------------------
extern "C" void kernel_launch(void* const* d_in, const int* in_sizes, int n_in,
                              void* d_out, int out_size) {
    const float* unary  = nullptr;   // 2*21*256*256 = 2752512
    const float* img    = nullptr;   // 2*3*256*256  = 393216
    const float* weight = nullptr;   // 21
    for (int i = 0; i < n_in; i++) {
        if (in_sizes[i] == BB*CC*HW)      unary  = (const float*)d_in[i];
        else if (in_sizes[i] == BB*3*HW)  img    = (const float*)d_in[i];
        else if (in_sizes[i] == CC)       weight = (const float*)d_in[i];
        // num_iter (1 elem) fixed at 5 by problem setup.
    }
    float* out = (float*)d_out;

    // allow 31.7 KB dynamic smem (host attribute; not an allocation; capture-safe)
    cudaFuncSetAttribute(iter2_kernel,
                         cudaFuncAttributeMaxDynamicSharedMemorySize, SMEM_DYN);

    dim3 blkA(32, GTH);
    dim3 grdA(WW/GTW, HH/GTH, BB);        // 4 x 32 x 2
    gauss_kernel<<<grdA, blkA>>>(img);
    lsm_kernel<<<(BB*HW + 255)/256, 256>>>(unary);

    dim3 blkC(32, 4);
    dim3 grdC(WW/T2W, HH/T2H, BB);        // 4 x 64 x 2 = 512 blocks
    for (int it = 0; it < 5; it++)
        iter2_kernel<<<grdC, blkC, SMEM_DYN>>>(weight, out, it);
}